// round 9
// baseline (speedup 1.0000x reference)
#include <cuda_runtime.h>
#include <cuda_bf16.h>
#include <stdint.h>

#define LOG2E 1.4426950408889634f
#define NBLK 148

__device__ float g_part[NBLK * 8192];

__device__ __forceinline__ uint32_t smem_u32(const void* p) {
    uint32_t a;
    asm("{ .reg .u64 t; cvta.to.shared.u64 t, %1; cvt.u32.u64 %0, t; }" : "=r"(a) : "l"(p));
    return a;
}
__device__ __forceinline__ float ex2f(float x) {
    float r; asm("ex2.approx.ftz.f32 %0, %1;" : "=f"(r) : "f"(x)); return r;
}
__device__ __forceinline__ uint32_t swz(uint32_t o) { return o ^ ((o >> 3) & 0x70u); }

__device__ __forceinline__ void ldm4(uint32_t a, uint32_t& r0, uint32_t& r1, uint32_t& r2, uint32_t& r3) {
    asm volatile("ldmatrix.sync.aligned.m8n8.x4.shared.b16 {%0,%1,%2,%3}, [%4];"
                 : "=r"(r0), "=r"(r1), "=r"(r2), "=r"(r3) : "r"(a));
}
__device__ __forceinline__ void ldm4t(uint32_t a, uint32_t& r0, uint32_t& r1, uint32_t& r2, uint32_t& r3) {
    asm volatile("ldmatrix.sync.aligned.m8n8.x4.trans.shared.b16 {%0,%1,%2,%3}, [%4];"
                 : "=r"(r0), "=r"(r1), "=r"(r2), "=r"(r3) : "r"(a));
}
__device__ __forceinline__ void mma16816(float* d, const uint32_t* a, uint32_t b0, uint32_t b1) {
    asm volatile("mma.sync.aligned.m16n8k16.row.col.f32.bf16.bf16.f32 "
                 "{%0,%1,%2,%3}, {%4,%5,%6,%7}, {%8,%9}, {%0,%1,%2,%3};"
                 : "+f"(d[0]), "+f"(d[1]), "+f"(d[2]), "+f"(d[3])
                 : "r"(a[0]), "r"(a[1]), "r"(a[2]), "r"(a[3]), "r"(b0), "r"(b1));
}

__device__ __forceinline__ uint32_t pk2(__nv_bfloat16 a, __nv_bfloat16 b) {
    __nv_bfloat162 t(a, b);
    return reinterpret_cast<uint32_t&>(t);
}
// split (v0,v1) into packed hi / packed lo bf16x2
__device__ __forceinline__ void split2(float v0, float v1, uint32_t& hi, uint32_t& lo) {
    __nv_bfloat16 h0 = __float2bfloat16(v0), h1 = __float2bfloat16(v1);
    hi = pk2(h0, h1);
    lo = pk2(__float2bfloat16(v0 - __bfloat162float(h0)),
             __float2bfloat16(v1 - __bfloat162float(h1)));
}

// split 32 floats (one row-half) into bf16 hi/lo, store SW128-swizzled (64 bf16 = 128B rows)
__device__ __forceinline__ void store_split(char* dh, char* dl, int row, int half, const float4* v) {
    uint32_t base = (uint32_t)row * 128u + (uint32_t)half * 64u;
#pragma unroll
    for (int j = 0; j < 8; j++) {
        float4 f = v[j];
        uint32_t h0, l0, h1, l1;
        split2(f.x, f.y, h0, l0);
        split2(f.z, f.w, h1, l1);
        uint32_t so = swz(base + (uint32_t)j * 8u);
        *reinterpret_cast<uint2*>(dh + so) = make_uint2(h0, h1);
        *reinterpret_cast<uint2*>(dl + so) = make_uint2(l0, l1);
    }
}

__global__ void __launch_bounds__(256, 1)
hist_kernel(const float* __restrict__ x, const float* __restrict__ cen, int ntiles) {
    __shared__ alignas(128) char sxh[16384];   // x hi tile: 128 rows(n) x 64 bf16(i)
    __shared__ alignas(128) char sxl[16384];   // x lo tile
    __shared__ float hx2s[128];                // 0.5*|x_n|^2*log2e
    __shared__ float hc2s[128];                // 0.5*|c_o|^2*log2e

    const int tid = threadIdx.x, wid = tid >> 5, lane = tid & 31;
    const int g = lane >> 2, t = lane & 3;
    const uint32_t xh_b = smem_u32(sxh), xl_b = smem_u32(sxl);
    const uint32_t lm = (uint32_t)(lane >> 3), lr = (uint32_t)(lane & 7);

    // center norms (prescaled)
    if (tid < 128) {
        const float4* p = reinterpret_cast<const float4*>(cen + (size_t)tid * 64);
        float s = 0.f;
#pragma unroll
        for (int j = 0; j < 16; j++) {
            float4 f = p[j];
            s += f.x * f.x + f.y * f.y + f.z * f.z + f.w * f.w;
        }
        hc2s[tid] = 0.5f * LOG2E * s;
    }

    // center A-fragments (resident in registers for the whole kernel)
    uint32_t ch[4][4], cl[4][4];
    const int ro = 16 * wid + g;
#pragma unroll
    for (int k = 0; k < 4; k++) {
        const float* b0 = cen + (size_t)ro * 64 + 16 * k + 2 * t;
        const float* b1 = cen + (size_t)(ro + 8) * 64 + 16 * k + 2 * t;
        float2 f0 = *reinterpret_cast<const float2*>(b0);
        float2 f1 = *reinterpret_cast<const float2*>(b1);
        float2 f2 = *reinterpret_cast<const float2*>(b0 + 8);
        float2 f3 = *reinterpret_cast<const float2*>(b1 + 8);
        split2(f0.x, f0.y, ch[k][0], cl[k][0]);
        split2(f1.x, f1.y, ch[k][1], cl[k][1]);
        split2(f2.x, f2.y, ch[k][2], cl[k][2]);
        split2(f3.x, f3.y, ch[k][3], cl[k][3]);
    }
    __syncthreads();
    const float hcA = hc2s[ro], hcB = hc2s[ro + 8];

    float acc2[8][4];   // hist: 16(o) x 64(i) per warp, accumulated over all tiles
#pragma unroll
    for (int i = 0; i < 8; i++)
#pragma unroll
        for (int q = 0; q < 4; q++) acc2[i][q] = 0.f;

    for (int tile = blockIdx.x; tile < ntiles; tile += gridDim.x) {
        // ---- stage x tile (LDGs issued before barrier -> overlap prior GEMM2) ----
        const int r = tid >> 1, half = tid & 1;
        const float4* p = reinterpret_cast<const float4*>(
            x + (size_t)(tile * 128 + r) * 64 + half * 32);
        float4 v[8];
#pragma unroll
        for (int j = 0; j < 8; j++) v[j] = p[j];
        __syncthreads();                       // prior iteration done reading smem
        float ss = 0.f;
#pragma unroll
        for (int j = 0; j < 8; j++)
            ss += v[j].x * v[j].x + v[j].y * v[j].y + v[j].z * v[j].z + v[j].w * v[j].w;
        float tot = ss + __shfl_xor_sync(0xFFFFFFFFu, ss, 1);
        if (half == 0) hx2s[r] = 0.5f * LOG2E * tot;
        store_split(sxh, sxl, r, half, v);
        __syncthreads();

        // ---- GEMM1: S[o,n] = C . X^T, split-bf16 3 passes ----
        float acc1[16][4];
#pragma unroll
        for (int i = 0; i < 16; i++)
#pragma unroll
            for (int q = 0; q < 4; q++) acc1[i][q] = 0.f;
#pragma unroll
        for (int jp = 0; jp < 8; jp++) {
#pragma unroll
            for (int k = 0; k < 4; k++) {
                uint32_t off = (16u * jp + (lm >> 1) * 8u + lr) * 128u + 32u * k + (lm & 1u) * 16u;
                uint32_t h0, h1, h2, h3, l0, l1, l2, l3;
                ldm4(xh_b + swz(off), h0, h1, h2, h3);
                ldm4(xl_b + swz(off), l0, l1, l2, l3);
                mma16816(acc1[2 * jp], ch[k], h0, h1);
                mma16816(acc1[2 * jp], ch[k], l0, l1);
                mma16816(acc1[2 * jp], cl[k], h0, h1);
                mma16816(acc1[2 * jp + 1], ch[k], h2, h3);
                mma16816(acc1[2 * jp + 1], ch[k], l2, l3);
                mma16816(acc1[2 * jp + 1], cl[k], h2, h3);
            }
        }

        // ---- epilogue (rbf in regs, C->A fragment reuse) + GEMM2 interleaved ----
#pragma unroll
        for (int kk = 0; kk < 8; kk++) {
            const int j0 = 2 * kk, j1 = j0 + 1;
            float2 hx0 = *reinterpret_cast<const float2*>(&hx2s[8 * j0 + 2 * t]);
            float2 hx1 = *reinterpret_cast<const float2*>(&hx2s[8 * j1 + 2 * t]);
            float v00 = ex2f(fmaf(acc1[j0][0], LOG2E, -hcA) - hx0.x);
            float v01 = ex2f(fmaf(acc1[j0][1], LOG2E, -hcA) - hx0.y);
            float v02 = ex2f(fmaf(acc1[j0][2], LOG2E, -hcB) - hx0.x);
            float v03 = ex2f(fmaf(acc1[j0][3], LOG2E, -hcB) - hx0.y);
            float v10 = ex2f(fmaf(acc1[j1][0], LOG2E, -hcA) - hx1.x);
            float v11 = ex2f(fmaf(acc1[j1][1], LOG2E, -hcA) - hx1.y);
            float v12 = ex2f(fmaf(acc1[j1][2], LOG2E, -hcB) - hx1.x);
            float v13 = ex2f(fmaf(acc1[j1][3], LOG2E, -hcB) - hx1.y);
            uint32_t ah[4], al[4];
            split2(v00, v01, ah[0], al[0]);
            split2(v02, v03, ah[1], al[1]);
            split2(v10, v11, ah[2], al[2]);
            split2(v12, v13, ah[3], al[3]);
#pragma unroll
            for (int ip = 0; ip < 4; ip++) {
                uint32_t off = (16u * kk + (lm & 1u) * 8u + lr) * 128u + 32u * ip + (lm >> 1) * 16u;
                uint32_t h0, h1, h2, h3, l0, l1, l2, l3;
                ldm4t(xh_b + swz(off), h0, h1, h2, h3);
                ldm4t(xl_b + swz(off), l0, l1, l2, l3);
                mma16816(acc2[2 * ip], ah, h0, h1);
                mma16816(acc2[2 * ip], ah, l0, l1);
                mma16816(acc2[2 * ip], al, h0, h1);
                mma16816(acc2[2 * ip + 1], ah, h2, h3);
                mma16816(acc2[2 * ip + 1], ah, l2, l3);
                mma16816(acc2[2 * ip + 1], al, h2, h3);
            }
        }
    }

    // ---- per-CTA partial writeout ----
    float* dst = g_part + (size_t)blockIdx.x * 8192;
#pragma unroll
    for (int ib = 0; ib < 8; ib++) {
        *reinterpret_cast<float2*>(dst + (size_t)ro * 64 + 8 * ib + 2 * t) =
            make_float2(acc2[ib][0], acc2[ib][1]);
        *reinterpret_cast<float2*>(dst + (size_t)(ro + 8) * 64 + 8 * ib + 2 * t) =
            make_float2(acc2[ib][2], acc2[ib][3]);
    }
}

__global__ void reduce_kernel(float* __restrict__ out) {
    int idx = blockIdx.x * blockDim.x + threadIdx.x;
    if (idx >= 8192) return;
    float s = 0.f;
#pragma unroll 4
    for (int b = 0; b < NBLK; b++) s += g_part[(size_t)b * 8192 + idx];
    out[idx] = s;
}

extern "C" void kernel_launch(void* const* d_in, const int* in_sizes, int n_in,
                              void* d_out, int out_size) {
    const float* x = (const float*)d_in[0];
    const float* c = (const float*)d_in[1];
    int N = in_sizes[0] / 64;
    int ntiles = N / 128;
    hist_kernel<<<NBLK, 256>>>(x, c, ntiles);
    reduce_kernel<<<32, 256>>>((float*)d_out);
}

// round 10
// speedup vs baseline: 1.0991x; 1.0991x over previous
#include <cuda_runtime.h>
#include <cuda_bf16.h>
#include <stdint.h>

#define LOG2E 1.4426950408889634f
#define MAXBLK 160

__device__ float g_part[MAXBLK * 8192];

__device__ __forceinline__ uint32_t smem_u32(const void* p) {
    uint32_t a;
    asm("{ .reg .u64 t; cvta.to.shared.u64 t, %1; cvt.u32.u64 %0, t; }" : "=r"(a) : "l"(p));
    return a;
}
__device__ __forceinline__ float ex2f(float x) {
    float r; asm("ex2.approx.ftz.f32 %0, %1;" : "=f"(r) : "f"(x)); return r;
}
__device__ __forceinline__ uint32_t swz(uint32_t o) { return o ^ ((o >> 3) & 0x70u); }

__device__ __forceinline__ void ldm4(uint32_t a, uint32_t& r0, uint32_t& r1, uint32_t& r2, uint32_t& r3) {
    asm volatile("ldmatrix.sync.aligned.m8n8.x4.shared.b16 {%0,%1,%2,%3}, [%4];"
                 : "=r"(r0), "=r"(r1), "=r"(r2), "=r"(r3) : "r"(a));
}
__device__ __forceinline__ void ldm4t(uint32_t a, uint32_t& r0, uint32_t& r1, uint32_t& r2, uint32_t& r3) {
    asm volatile("ldmatrix.sync.aligned.m8n8.x4.trans.shared.b16 {%0,%1,%2,%3}, [%4];"
                 : "=r"(r0), "=r"(r1), "=r"(r2), "=r"(r3) : "r"(a));
}
__device__ __forceinline__ void mma16816(float* d, const uint32_t* a, uint32_t b0, uint32_t b1) {
    asm volatile("mma.sync.aligned.m16n8k16.row.col.f32.bf16.bf16.f32 "
                 "{%0,%1,%2,%3}, {%4,%5,%6,%7}, {%8,%9}, {%0,%1,%2,%3};"
                 : "+f"(d[0]), "+f"(d[1]), "+f"(d[2]), "+f"(d[3])
                 : "r"(a[0]), "r"(a[1]), "r"(a[2]), "r"(a[3]), "r"(b0), "r"(b1));
}

// packed split: hi = bf16x2(v1|v0), lo = bf16x2 of exact residuals
__device__ __forceinline__ void split2(float v0, float v1, uint32_t& hi, uint32_t& lo) {
    uint32_t h;
    asm("cvt.rn.bf16x2.f32 %0, %1, %2;" : "=r"(h) : "f"(v1), "f"(v0));
    float h0 = __uint_as_float(h << 16);
    float h1 = __uint_as_float(h & 0xffff0000u);
    float r0 = v0 - h0, r1 = v1 - h1;
    asm("cvt.rn.bf16x2.f32 %0, %1, %2;" : "=r"(lo) : "f"(r1), "f"(r0));
    hi = h;
}

// split 32 floats (one row-half) into bf16 hi/lo, store SW128-swizzled (64 bf16 = 128B rows)
__device__ __forceinline__ void store_split(char* dh, char* dl, int row, int half, const float4* v) {
    uint32_t base = (uint32_t)row * 128u + (uint32_t)half * 64u;
#pragma unroll
    for (int j = 0; j < 8; j++) {
        float4 f = v[j];
        uint32_t h0, l0, h1, l1;
        split2(f.x, f.y, h0, l0);
        split2(f.z, f.w, h1, l1);
        uint32_t so = swz(base + (uint32_t)j * 8u);
        *reinterpret_cast<uint2*>(dh + so) = make_uint2(h0, h1);
        *reinterpret_cast<uint2*>(dl + so) = make_uint2(l0, l1);
    }
}

__global__ void __launch_bounds__(256, 1)
hist_kernel(const float* __restrict__ x, const float* __restrict__ cen, int ntiles) {
    __shared__ alignas(128) char sxh[16384];   // x hi tile: 128 rows(n) x 64 bf16(i)
    __shared__ alignas(128) char sxl[16384];   // x lo tile
    __shared__ float hx2s[128];                // 0.5*|x_n|^2*log2e
    __shared__ float hc2s[128];                // 0.5*|c_o|^2*log2e

    const int tid = threadIdx.x, wid = tid >> 5, lane = tid & 31;
    const int g = lane >> 2, t = lane & 3;
    const uint32_t xh_b = smem_u32(sxh), xl_b = smem_u32(sxl);
    const uint32_t lm = (uint32_t)(lane >> 3), lr = (uint32_t)(lane & 7);

    // center norms (prescaled)
    if (tid < 128) {
        const float4* p = reinterpret_cast<const float4*>(cen + (size_t)tid * 64);
        float s = 0.f;
#pragma unroll
        for (int j = 0; j < 16; j++) {
            float4 f = p[j];
            s += f.x * f.x + f.y * f.y + f.z * f.z + f.w * f.w;
        }
        hc2s[tid] = 0.5f * LOG2E * s;
    }

    // center A-fragments (resident in registers for the whole kernel)
    uint32_t ch[4][4], cl[4][4];
    const int ro = 16 * wid + g;
#pragma unroll
    for (int k = 0; k < 4; k++) {
        const float* b0 = cen + (size_t)ro * 64 + 16 * k + 2 * t;
        const float* b1 = cen + (size_t)(ro + 8) * 64 + 16 * k + 2 * t;
        float2 f0 = *reinterpret_cast<const float2*>(b0);
        float2 f1 = *reinterpret_cast<const float2*>(b1);
        float2 f2 = *reinterpret_cast<const float2*>(b0 + 8);
        float2 f3 = *reinterpret_cast<const float2*>(b1 + 8);
        split2(f0.x, f0.y, ch[k][0], cl[k][0]);
        split2(f1.x, f1.y, ch[k][1], cl[k][1]);
        split2(f2.x, f2.y, ch[k][2], cl[k][2]);
        split2(f3.x, f3.y, ch[k][3], cl[k][3]);
    }
    __syncthreads();
    const float hcA = hc2s[ro], hcB = hc2s[ro + 8];

    float acc2[8][4];   // hist: 16(o) x 64(i) per warp, accumulated over all tiles
#pragma unroll
    for (int i = 0; i < 8; i++)
#pragma unroll
        for (int q = 0; q < 4; q++) acc2[i][q] = 0.f;

    for (int tile = blockIdx.x; tile < ntiles; tile += gridDim.x) {
        // ---- stage x tile (LDGs issued before barrier -> overlap prior GEMM2) ----
        const int r = tid >> 1, half = tid & 1;
        const float4* p = reinterpret_cast<const float4*>(
            x + (size_t)(tile * 128 + r) * 64 + half * 32);
        float4 v[8];
#pragma unroll
        for (int j = 0; j < 8; j++) v[j] = p[j];
        __syncthreads();                       // prior iteration done reading smem
        float ss = 0.f;
#pragma unroll
        for (int j = 0; j < 8; j++)
            ss += v[j].x * v[j].x + v[j].y * v[j].y + v[j].z * v[j].z + v[j].w * v[j].w;
        float tot = ss + __shfl_xor_sync(0xFFFFFFFFu, ss, 1);
        if (half == 0) hx2s[r] = 0.5f * LOG2E * tot;
        store_split(sxh, sxl, r, half, v);
        __syncthreads();

        // ---- GEMM1: S[o,n] = C . X^T, split-bf16 3 passes ----
        float acc1[16][4];
#pragma unroll
        for (int i = 0; i < 16; i++)
#pragma unroll
            for (int q = 0; q < 4; q++) acc1[i][q] = 0.f;
#pragma unroll
        for (int jp = 0; jp < 8; jp++) {
#pragma unroll
            for (int k = 0; k < 4; k++) {
                uint32_t off = (16u * jp + (lm >> 1) * 8u + lr) * 128u + 32u * k + (lm & 1u) * 16u;
                uint32_t h0, h1, h2, h3, l0, l1, l2, l3;
                ldm4(xh_b + swz(off), h0, h1, h2, h3);
                ldm4(xl_b + swz(off), l0, l1, l2, l3);
                mma16816(acc1[2 * jp], ch[k], h0, h1);
                mma16816(acc1[2 * jp], ch[k], l0, l1);
                mma16816(acc1[2 * jp], cl[k], h0, h1);
                mma16816(acc1[2 * jp + 1], ch[k], h2, h3);
                mma16816(acc1[2 * jp + 1], ch[k], l2, l3);
                mma16816(acc1[2 * jp + 1], cl[k], h2, h3);
            }
        }

        // ---- epilogue (rbf in regs, C->A fragment reuse) + GEMM2 interleaved ----
#pragma unroll
        for (int kk = 0; kk < 8; kk++) {
            const int j0 = 2 * kk, j1 = j0 + 1;
            float2 hx0 = *reinterpret_cast<const float2*>(&hx2s[8 * j0 + 2 * t]);
            float2 hx1 = *reinterpret_cast<const float2*>(&hx2s[8 * j1 + 2 * t]);
            float v00 = ex2f(fmaf(acc1[j0][0], LOG2E, -hcA) - hx0.x);
            float v01 = ex2f(fmaf(acc1[j0][1], LOG2E, -hcA) - hx0.y);
            float v02 = ex2f(fmaf(acc1[j0][2], LOG2E, -hcB) - hx0.x);
            float v03 = ex2f(fmaf(acc1[j0][3], LOG2E, -hcB) - hx0.y);
            float v10 = ex2f(fmaf(acc1[j1][0], LOG2E, -hcA) - hx1.x);
            float v11 = ex2f(fmaf(acc1[j1][1], LOG2E, -hcA) - hx1.y);
            float v12 = ex2f(fmaf(acc1[j1][2], LOG2E, -hcB) - hx1.x);
            float v13 = ex2f(fmaf(acc1[j1][3], LOG2E, -hcB) - hx1.y);
            uint32_t ah[4], al[4];
            split2(v00, v01, ah[0], al[0]);
            split2(v02, v03, ah[1], al[1]);
            split2(v10, v11, ah[2], al[2]);
            split2(v12, v13, ah[3], al[3]);
#pragma unroll
            for (int ip = 0; ip < 4; ip++) {
                uint32_t off = (16u * kk + (lm & 1u) * 8u + lr) * 128u + 32u * ip + (lm >> 1) * 16u;
                uint32_t h0, h1, h2, h3, l0, l1, l2, l3;
                ldm4t(xh_b + swz(off), h0, h1, h2, h3);
                ldm4t(xl_b + swz(off), l0, l1, l2, l3);
                mma16816(acc2[2 * ip], ah, h0, h1);
                mma16816(acc2[2 * ip], ah, l0, l1);
                mma16816(acc2[2 * ip], al, h0, h1);
                mma16816(acc2[2 * ip + 1], ah, h2, h3);
                mma16816(acc2[2 * ip + 1], ah, l2, l3);
                mma16816(acc2[2 * ip + 1], al, h2, h3);
            }
        }
    }

    // ---- per-CTA partial writeout ----
    float* dst = g_part + (size_t)blockIdx.x * 8192;
#pragma unroll
    for (int ib = 0; ib < 8; ib++) {
        *reinterpret_cast<float2*>(dst + (size_t)ro * 64 + 8 * ib + 2 * t) =
            make_float2(acc2[ib][0], acc2[ib][1]);
        *reinterpret_cast<float2*>(dst + (size_t)(ro + 8) * 64 + 8 * ib + 2 * t) =
            make_float2(acc2[ib][2], acc2[ib][3]);
    }
}

// 256 blocks x 256 thr: block owns 32 outputs; 8 chunks of partials per output,
// fixed-order combine -> deterministic. Coalesced 128B per warp.
__global__ void reduce_kernel(float* __restrict__ out, int nblk) {
    __shared__ float red[256];
    const int o = blockIdx.x * 32 + (threadIdx.x & 31);
    const int chunk = threadIdx.x >> 5;
    const int per = (nblk + 7) >> 3;
    const int b0 = chunk * per;
    const int b1 = (b0 + per < nblk) ? (b0 + per) : nblk;
    float s = 0.f;
#pragma unroll 4
    for (int b = b0; b < b1; b++) s += g_part[(size_t)b * 8192 + o];
    red[threadIdx.x] = s;
    __syncthreads();
    if (threadIdx.x < 32) {
        float tsum = red[threadIdx.x];
#pragma unroll
        for (int c = 1; c < 8; c++) tsum += red[c * 32 + threadIdx.x];
        out[o] = tsum;
    }
}

extern "C" void kernel_launch(void* const* d_in, const int* in_sizes, int n_in,
                              void* d_out, int out_size) {
    const float* x = (const float*)d_in[0];
    const float* c = (const float*)d_in[1];
    int N = in_sizes[0] / 64;
    int ntiles = N / 128;
    int dev = 0, sm = 0, nblk = 148;
    if (cudaGetDevice(&dev) == cudaSuccess &&
        cudaDeviceGetAttribute(&sm, cudaDevAttrMultiProcessorCount, dev) == cudaSuccess &&
        sm > 0) {
        nblk = sm > MAXBLK ? MAXBLK : sm;
    }
    if (nblk > ntiles) nblk = ntiles;
    hist_kernel<<<nblk, 256>>>(x, c, ntiles);
    reduce_kernel<<<256, 256>>>((float*)d_out, nblk);
}